// round 6
// baseline (speedup 1.0000x reference)
#include <cuda_runtime.h>

// NavierStokesPINN1 — ReLU MLP is piecewise linear, so all Hessian terms in
// f,g vanish under JAX autodiff:
//   u = dpsi/dy, v = -dpsi/dx, p, f = dp/dx, g = dp/dy.
// Accuracy model (R3/R4 evidence): the reference is exact fp32; rel_err is
// dominated by ReLU-mask flips caused by accumulation-ORDER differences in
// the preactivations. Fix: reproduce XLA/cublas rounding exactly —
// single accumulator, k ascending, FMA per step, bias added AFTER the
// reduction, then relu. This makes the forward pass (and hence every mask)
// bit-identical to the reference. Derivatives via reverse mode (2 cotangent
// streams through pre-transposed weights), matching jax.grad's structure.

#define H        256
#define NL       4
#define NPTS     65536
#define WP       2                  // points per warp
#define THREADS  256
#define PTS_PER_CTA 16              // 8 warps * WP
#define CHUNK    32                 // k-rows staged per smem chunk
#define CHUNK_FLOATS (CHUNK * H)    // 8192 floats = 32KB

// Scratch: transposed hidden weights for the backward pass.
__device__ float g_WhT[NL * H * H];

__device__ __forceinline__ void cp_async16(void* s, const void* g) {
    unsigned sa = (unsigned)__cvta_generic_to_shared(s);
    asm volatile("cp.async.cg.shared.global [%0], [%1], 16;" :: "r"(sa), "l"(g));
}
__device__ __forceinline__ void cp_commit() { asm volatile("cp.async.commit_group;"); }
template<int NN> __device__ __forceinline__ void cp_wait() {
    asm volatile("cp.async.wait_group %0;" :: "n"(NN));
}

__device__ __forceinline__ void stage_chunk(float* dst, const float* src, int tid) {
    #pragma unroll
    for (int q = 0; q < CHUNK_FLOATS / 4 / THREADS; ++q) {   // 8 float4 per thread
        int fi = q * THREADS + tid;
        cp_async16(((float4*)dst) + fi, ((const float4*)src) + fi);
    }
    cp_commit();
}

// Global chunk schedule: chunks 0..31 = Wh layers 0..3 (forward, natural
// layout), chunks 32..63 = g_WhT layers 3,2,1,0 (backward).
__device__ __forceinline__ const float* chunk_src(int c, const float* Wh) {
    if (c < 32) return Wh + c * CHUNK_FLOATS;
    int cc = c - 32;
    int l = 3 - (cc >> 3);
    return g_WhT + (l * 8 + (cc & 7)) * CHUNK_FLOATS;
}

__global__ void prep_kernel(const float* __restrict__ Wh) {
    int i = blockIdx.x * blockDim.x + threadIdx.x;   // NL*H*H = 262144 threads
    float v = __ldg(Wh + i);
    int l = i >> 16;
    int rem = i & 0xFFFF;
    int k = rem >> 8, j = rem & 0xFF;
    g_WhT[(l << 16) + (j << 8) + k] = v;   // WhT[l][j][k] = Wh[l][k][j]
}

// Neuron ownership: lane owns j = 128*g + 4*lane + c for g in {0,1}, c in 0..3
// (two float4 groups), local index i = 4*g + c.
#define JIDX(i) ((((i) >> 2) << 7) + (lane << 2) + ((i) & 3))

__global__ void __launch_bounds__(THREADS, 2)
pinn_kernel(const float* __restrict__ x, const float* __restrict__ y,
            const float* __restrict__ t,
            const float* __restrict__ Win,  const float* __restrict__ b_in,
            const float* __restrict__ Wh,   const float* __restrict__ b_h,
            const float* __restrict__ Wout, const float* __restrict__ b_out,
            float* __restrict__ out)
{
    extern __shared__ float Ws[];   // [2][CHUNK][H] double-buffered
    const int tid  = threadIdx.x;
    const int lane = tid & 31;
    const int warp = tid >> 5;
    const int base = blockIdx.x * PTS_PER_CTA + warp * WP;

    stage_chunk(Ws, chunk_src(0, Wh), tid);   // prefetch forward layer0 chunk0

    // ------- input layer: GEMM order (k ascending, acc from 0), bias AFTER -------
    float h[WP][8];
    unsigned mi[WP] = {0u, 0u};     // input-layer masks, 8 bits per point
    float rx[WP], ry[WP], rt[WP];
    #pragma unroll
    for (int p = 0; p < WP; ++p) {
        rx[p] = x[base + p]; ry[p] = y[base + p]; rt[p] = t[base + p];
    }
    #pragma unroll
    for (int i = 0; i < 8; ++i) {
        int j = JIDX(i);
        float w0 = __ldg(Win + j);
        float w1 = __ldg(Win + H + j);
        float w2 = __ldg(Win + 2 * H + j);
        float bb = __ldg(b_in + j);
        #pragma unroll
        for (int p = 0; p < WP; ++p) {
            float acc = fmaf(rx[p], w0, 0.f);   // k=0
            acc = fmaf(ry[p], w1, acc);         // k=1
            acc = fmaf(rt[p], w2, acc);         // k=2
            float a = acc + bb;                 // bias after reduction
            bool m = a > 0.f;
            mi[p] |= (unsigned)m << i;
            h[p][i] = m ? a : 0.f;
        }
    }

    // ---------------- forward hidden layers ----------------
    unsigned mh[WP] = {0u, 0u};     // 4 layers x 8 bits per point
    int c = 0;                       // global chunk id under compute

    #pragma unroll 1
    for (int l = 0; l < NL; ++l) {
        float acc[WP][8];
        #pragma unroll
        for (int i = 0; i < 8; ++i) {
            #pragma unroll
            for (int p = 0; p < WP; ++p) acc[p][i] = 0.f;   // GEMM beta=0
        }

        #pragma unroll 2
        for (int r = 0; r < 8; ++r, ++c) {
            stage_chunk(Ws + ((r + 1) & 1) * CHUNK_FLOATS, chunk_src(c + 1, Wh), tid);
            cp_wait<1>();
            __syncthreads();

            float hv0[4], hv1[4];   // hoisted group-select for broadcast source
            #pragma unroll
            for (int e = 0; e < 4; ++e) {
                hv0[e] = (r >= 4) ? h[0][4 + e] : h[0][e];
                hv1[e] = (r >= 4) ? h[1][4 + e] : h[1][e];
            }
            const float* wb = Ws + (r & 1) * CHUNK_FLOATS + (lane << 2);
            #pragma unroll 4
            for (int kl = 0; kl < CHUNK; ++kl) {
                int ol = ((r & 3) << 3) + (kl >> 2);
                int e  = kl & 3;
                float b0 = __shfl_sync(0xffffffffu, hv0[e], ol);
                float b1 = __shfl_sync(0xffffffffu, hv1[e], ol);
                float4 wA = *(const float4*)(wb + kl * H);
                float4 wB = *(const float4*)(wb + kl * H + 128);
                acc[0][0] = fmaf(b0, wA.x, acc[0][0]);
                acc[0][1] = fmaf(b0, wA.y, acc[0][1]);
                acc[0][2] = fmaf(b0, wA.z, acc[0][2]);
                acc[0][3] = fmaf(b0, wA.w, acc[0][3]);
                acc[0][4] = fmaf(b0, wB.x, acc[0][4]);
                acc[0][5] = fmaf(b0, wB.y, acc[0][5]);
                acc[0][6] = fmaf(b0, wB.z, acc[0][6]);
                acc[0][7] = fmaf(b0, wB.w, acc[0][7]);
                acc[1][0] = fmaf(b1, wA.x, acc[1][0]);
                acc[1][1] = fmaf(b1, wA.y, acc[1][1]);
                acc[1][2] = fmaf(b1, wA.z, acc[1][2]);
                acc[1][3] = fmaf(b1, wA.w, acc[1][3]);
                acc[1][4] = fmaf(b1, wB.x, acc[1][4]);
                acc[1][5] = fmaf(b1, wB.y, acc[1][5]);
                acc[1][6] = fmaf(b1, wB.z, acc[1][6]);
                acc[1][7] = fmaf(b1, wB.w, acc[1][7]);
            }
            __syncthreads();
        }

        // bias AFTER reduction, then relu; record mask
        #pragma unroll
        for (int i = 0; i < 8; ++i) {
            float bb = __ldg(b_h + l * H + JIDX(i));
            #pragma unroll
            for (int p = 0; p < WP; ++p) {
                float a = acc[p][i] + bb;
                bool m = a > 0.f;
                mh[p] |= (unsigned)m << (l * 8 + i);
                h[p][i] = m ? a : 0.f;
            }
        }
    }

    // p = h4 . wout[:,1] + b_out[1]
    float pp[WP] = {0.f, 0.f};
    #pragma unroll
    for (int i = 0; i < 8; ++i) {
        float wo1 = __ldg(Wout + 2 * JIDX(i) + 1);
        #pragma unroll
        for (int p = 0; p < WP; ++p) pp[p] = fmaf(h[p][i], wo1, pp[p]);
    }

    // ---------------- backward: 2 cotangent streams (psi, p) ----------------
    float gg0[WP][8], gg1[WP][8];
    #pragma unroll
    for (int i = 0; i < 8; ++i) {
        float a0 = __ldg(Wout + 2 * JIDX(i));       // wout[:,0] -> psi
        float a1 = __ldg(Wout + 2 * JIDX(i) + 1);   // wout[:,1] -> p
        #pragma unroll
        for (int p = 0; p < WP; ++p) { gg0[p][i] = a0; gg1[p][i] = a1; }
    }

    #pragma unroll 1
    for (int bl = 3; bl >= 0; --bl) {
        float rb0[WP][8], rb1[WP][8];   // mask * g: broadcast sources
        #pragma unroll
        for (int i = 0; i < 8; ++i) {
            #pragma unroll
            for (int p = 0; p < WP; ++p) {
                bool m = (mh[p] >> (bl * 8 + i)) & 1u;
                rb0[p][i] = m ? gg0[p][i] : 0.f;
                rb1[p][i] = m ? gg1[p][i] : 0.f;
            }
        }
        float na0[WP][8], na1[WP][8];
        #pragma unroll
        for (int i = 0; i < 8; ++i) {
            #pragma unroll
            for (int p = 0; p < WP; ++p) { na0[p][i] = 0.f; na1[p][i] = 0.f; }
        }

        #pragma unroll 2
        for (int r = 0; r < 8; ++r, ++c) {
            if (c < 63) {
                stage_chunk(Ws + ((r + 1) & 1) * CHUNK_FLOATS, chunk_src(c + 1, Wh), tid);
                cp_wait<1>();
            } else {
                cp_wait<0>();
            }
            __syncthreads();

            float s00[4], s01[4], s10[4], s11[4];
            #pragma unroll
            for (int e = 0; e < 4; ++e) {
                s00[e] = (r >= 4) ? rb0[0][4 + e] : rb0[0][e];
                s01[e] = (r >= 4) ? rb0[1][4 + e] : rb0[1][e];
                s10[e] = (r >= 4) ? rb1[0][4 + e] : rb1[0][e];
                s11[e] = (r >= 4) ? rb1[1][4 + e] : rb1[1][e];
            }
            const float* wb = Ws + (r & 1) * CHUNK_FLOATS + (lane << 2);
            #pragma unroll 4
            for (int kl = 0; kl < CHUNK; ++kl) {
                int ol = ((r & 3) << 3) + (kl >> 2);
                int e  = kl & 3;
                float b00 = __shfl_sync(0xffffffffu, s00[e], ol);
                float b01 = __shfl_sync(0xffffffffu, s01[e], ol);
                float b10 = __shfl_sync(0xffffffffu, s10[e], ol);
                float b11 = __shfl_sync(0xffffffffu, s11[e], ol);
                float4 wA = *(const float4*)(wb + kl * H);
                float4 wB = *(const float4*)(wb + kl * H + 128);
                na0[0][0] = fmaf(b00, wA.x, na0[0][0]);
                na0[0][1] = fmaf(b00, wA.y, na0[0][1]);
                na0[0][2] = fmaf(b00, wA.z, na0[0][2]);
                na0[0][3] = fmaf(b00, wA.w, na0[0][3]);
                na0[0][4] = fmaf(b00, wB.x, na0[0][4]);
                na0[0][5] = fmaf(b00, wB.y, na0[0][5]);
                na0[0][6] = fmaf(b00, wB.z, na0[0][6]);
                na0[0][7] = fmaf(b00, wB.w, na0[0][7]);
                na0[1][0] = fmaf(b01, wA.x, na0[1][0]);
                na0[1][1] = fmaf(b01, wA.y, na0[1][1]);
                na0[1][2] = fmaf(b01, wA.z, na0[1][2]);
                na0[1][3] = fmaf(b01, wA.w, na0[1][3]);
                na0[1][4] = fmaf(b01, wB.x, na0[1][4]);
                na0[1][5] = fmaf(b01, wB.y, na0[1][5]);
                na0[1][6] = fmaf(b01, wB.z, na0[1][6]);
                na0[1][7] = fmaf(b01, wB.w, na0[1][7]);
                na1[0][0] = fmaf(b10, wA.x, na1[0][0]);
                na1[0][1] = fmaf(b10, wA.y, na1[0][1]);
                na1[0][2] = fmaf(b10, wA.z, na1[0][2]);
                na1[0][3] = fmaf(b10, wA.w, na1[0][3]);
                na1[0][4] = fmaf(b10, wB.x, na1[0][4]);
                na1[0][5] = fmaf(b10, wB.y, na1[0][5]);
                na1[0][6] = fmaf(b10, wB.z, na1[0][6]);
                na1[0][7] = fmaf(b10, wB.w, na1[0][7]);
                na1[1][0] = fmaf(b11, wA.x, na1[1][0]);
                na1[1][1] = fmaf(b11, wA.y, na1[1][1]);
                na1[1][2] = fmaf(b11, wA.z, na1[1][2]);
                na1[1][3] = fmaf(b11, wA.w, na1[1][3]);
                na1[1][4] = fmaf(b11, wB.x, na1[1][4]);
                na1[1][5] = fmaf(b11, wB.y, na1[1][5]);
                na1[1][6] = fmaf(b11, wB.z, na1[1][6]);
                na1[1][7] = fmaf(b11, wB.w, na1[1][7]);
            }
            __syncthreads();
        }

        #pragma unroll
        for (int i = 0; i < 8; ++i) {
            #pragma unroll
            for (int p = 0; p < WP; ++p) { gg0[p][i] = na0[p][i]; gg1[p][i] = na1[p][i]; }
        }
    }

    // ---------------- input-layer backward + outputs ----------------
    float su[WP], sv[WP], sf[WP], sg[WP];
    #pragma unroll
    for (int p = 0; p < WP; ++p) { su[p] = sv[p] = sf[p] = sg[p] = 0.f; }

    #pragma unroll
    for (int i = 0; i < 8; ++i) {
        int j = JIDX(i);
        float wx = __ldg(Win + j);        // d/dx row
        float wy = __ldg(Win + H + j);    // d/dy row
        #pragma unroll
        for (int p = 0; p < WP; ++p) {
            bool m = (mi[p] >> i) & 1u;
            float r0 = m ? gg0[p][i] : 0.f;   // psi cotangent at input acts
            float r1 = m ? gg1[p][i] : 0.f;   // p cotangent
            su[p] = fmaf(wy, r0, su[p]);   // dpsi/dy = u
            sv[p] = fmaf(wx, r0, sv[p]);   // dpsi/dx = -v
            sf[p] = fmaf(wx, r1, sf[p]);   // dp/dx = f
            sg[p] = fmaf(wy, r1, sg[p]);   // dp/dy = g
        }
    }

    #pragma unroll
    for (int off = 16; off > 0; off >>= 1) {
        #pragma unroll
        for (int p = 0; p < WP; ++p) {
            su[p] += __shfl_xor_sync(0xffffffffu, su[p], off);
            sv[p] += __shfl_xor_sync(0xffffffffu, sv[p], off);
            sf[p] += __shfl_xor_sync(0xffffffffu, sf[p], off);
            sg[p] += __shfl_xor_sync(0xffffffffu, sg[p], off);
            pp[p] += __shfl_xor_sync(0xffffffffu, pp[p], off);
        }
    }
    if (lane == 0) {
        float bo1 = __ldg(b_out + 1);
        #pragma unroll
        for (int p = 0; p < WP; ++p) {
            int pt = base + p;
            out[0 * NPTS + pt] =  su[p];
            out[1 * NPTS + pt] = -sv[p];
            out[2 * NPTS + pt] =  pp[p] + bo1;
            out[3 * NPTS + pt] =  sf[p];
            out[4 * NPTS + pt] =  sg[p];
        }
    }
}

extern "C" void kernel_launch(void* const* d_in, const int* in_sizes, int n_in,
                              void* d_out, int out_size)
{
    const float* x     = (const float*)d_in[0];
    const float* y     = (const float*)d_in[1];
    const float* t     = (const float*)d_in[2];
    const float* Win   = (const float*)d_in[3];
    const float* b_in  = (const float*)d_in[4];
    const float* Wh    = (const float*)d_in[5];
    const float* b_h   = (const float*)d_in[6];
    const float* Wout  = (const float*)d_in[7];
    const float* b_out = (const float*)d_in[8];
    float* out = (float*)d_out;

    prep_kernel<<<(NL * H * H) / THREADS, THREADS>>>(Wh);

    const int smem = 2 * CHUNK_FLOATS * (int)sizeof(float);  // 64KB
    cudaFuncSetAttribute(pinn_kernel, cudaFuncAttributeMaxDynamicSharedMemorySize, smem);
    pinn_kernel<<<NPTS / PTS_PER_CTA, THREADS, smem>>>(x, y, t, Win, b_in, Wh, b_h,
                                                       Wout, b_out, out);
}

// round 7
// speedup vs baseline: 1.4624x; 1.4624x over previous
#include <cuda_runtime.h>

// NavierStokesPINN1 — ReLU MLP is piecewise linear; outputs reduce to
//   u = dpsi/dy, v = -dpsi/dx, p, f = dp/dx, g = dp/dy.
// Forward pass reproduces the reference's fp32 rounding exactly (single acc,
// k ascending, fma per step, bias after reduction) so every ReLU mask matches.
// R7: packed fp32 math (fma.rn.f32x2, 2 MACs/lane) + 8 points/warp with
// activations/cotangents broadcast from per-warp smem tables (LDS.64, N=1)
// instead of shuffles. Backward = 2 cotangent streams via transposed weights.

#define H        256
#define NL       4
#define NPTS     65536
#define WP       8                  // points per warp (4 packed pairs)
#define THREADS  256
#define WARPS    8
#define PTS_PER_CTA (WARPS * WP)    // 64
#define CHUNK    32
#define CHUNK_FLOATS (CHUNK * H)    // 8192 floats = 32KB

typedef unsigned long long u64;

__device__ float g_WhT[NL * H * H];   // transposed hidden weights (backward)

__device__ __forceinline__ u64 pack2(float lo, float hi) {
    u64 r; asm("mov.b64 %0, {%1, %2};" : "=l"(r) : "f"(lo), "f"(hi)); return r;
}
__device__ __forceinline__ void unpack2(u64 v, float& lo, float& hi) {
    asm("mov.b64 {%0, %1}, %2;" : "=f"(lo), "=f"(hi) : "l"(v));
}
__device__ __forceinline__ u64 ffma2(u64 a, u64 b, u64 c) {
    u64 d; asm("fma.rn.f32x2 %0, %1, %2, %3;" : "=l"(d) : "l"(a), "l"(b), "l"(c));
    return d;
}

__device__ __forceinline__ void cp_async16(void* s, const void* g) {
    unsigned sa = (unsigned)__cvta_generic_to_shared(s);
    asm volatile("cp.async.cg.shared.global [%0], [%1], 16;" :: "r"(sa), "l"(g));
}
__device__ __forceinline__ void cp_commit() { asm volatile("cp.async.commit_group;"); }
template<int NN> __device__ __forceinline__ void cp_wait() {
    asm volatile("cp.async.wait_group %0;" :: "n"(NN));
}

__device__ __forceinline__ void stage_chunk(float* dst, const float* src, int tid) {
    #pragma unroll
    for (int q = 0; q < CHUNK_FLOATS / 4 / THREADS; ++q) {
        int fi = q * THREADS + tid;
        cp_async16(((float4*)dst) + fi, ((const float4*)src) + fi);
    }
    cp_commit();
}

// chunks 0..31 = Wh layers 0..3 (forward), 32..63 = g_WhT layers 3,2,1,0.
__device__ __forceinline__ const float* chunk_src(int c, const float* Wh) {
    if (c < 32) return Wh + c * CHUNK_FLOATS;
    int cc = c - 32;
    int l = 3 - (cc >> 3);
    return g_WhT + (l * 8 + (cc & 7)) * CHUNK_FLOATS;
}

__global__ void prep_kernel(const float* __restrict__ Wh) {
    int i = blockIdx.x * blockDim.x + threadIdx.x;
    float v = __ldg(Wh + i);
    int l = i >> 16;
    int rem = i & 0xFFFF;
    int k = rem >> 8, j = rem & 0xFF;
    g_WhT[(l << 16) + (j << 8) + k] = v;
}

// lane owns neurons j = 128*(i>>2) + 4*lane + (i&3), i = 0..7
#define JIDX(i) ((((i) >> 2) << 7) + (lane << 2) + ((i) & 3))
// mask bit for (neuron-slot i, pair q, half h)
#define MBIT(i, q, hh) ((u64)1 << (((i) << 3) + ((q) << 1) + (hh)))

__global__ void __launch_bounds__(THREADS, 1)
pinn_kernel(const float* __restrict__ x, const float* __restrict__ y,
            const float* __restrict__ t,
            const float* __restrict__ Win,  const float* __restrict__ b_in,
            const float* __restrict__ Wh,   const float* __restrict__ b_h,
            const float* __restrict__ Wout, const float* __restrict__ b_out,
            float* __restrict__ out)
{
    extern __shared__ float Ws[];   // [2][CHUNK][H] weights + tables after
    const int tid  = threadIdx.x;
    const int lane = tid & 31;
    const int warp = tid >> 5;
    const int base = blockIdx.x * PTS_PER_CTA + warp * WP;

    // tables live after the 64KB weight double-buffer
    u64* tabA = (u64*)(Ws + 2 * CHUNK_FLOATS);
    u64* tabF = tabA + warp * 1024;          // fwd: 4 pairs x 256 neurons
    u64* tb0  = tabA + warp * 2048;          // bwd stream 0 (psi) — overlaps fwd
    u64* tb1  = tb0 + 1024;                  // bwd stream 1 (p)

    stage_chunk(Ws, chunk_src(0, Wh), tid);

    // ---------------- input layer (exact GEMM rounding order) ----------------
    u64 Mi = 0;          // input-layer masks
    u64 Mh[NL];          // hidden-layer masks
    {
        float rx[WP], ry[WP], rt[WP];
        #pragma unroll
        for (int p = 0; p < WP; ++p) {
            rx[p] = x[base + p]; ry[p] = y[base + p]; rt[p] = t[base + p];
        }
        #pragma unroll
        for (int i = 0; i < 8; ++i) {
            int j = JIDX(i);
            float w0 = __ldg(Win + j);
            float w1 = __ldg(Win + H + j);
            float w2 = __ldg(Win + 2 * H + j);
            float bb = __ldg(b_in + j);
            float hv[WP];
            #pragma unroll
            for (int p = 0; p < WP; ++p) {
                float acc = fmaf(rx[p], w0, 0.f);
                acc = fmaf(ry[p], w1, acc);
                acc = fmaf(rt[p], w2, acc);
                float a = acc + bb;
                bool m = a > 0.f;
                Mi |= m ? MBIT(i, p >> 1, p & 1) : 0ull;
                hv[p] = m ? a : 0.f;
            }
            #pragma unroll
            for (int q = 0; q < 4; ++q)
                tabF[(q << 8) + j] = pack2(hv[2 * q], hv[2 * q + 1]);
        }
    }
    __syncwarp();

    // ---------------- forward hidden layers ----------------
    u64 ppq[4] = {0ull, 0ull, 0ull, 0ull};   // packed p-output partials
    int c = 0;

    #pragma unroll 1
    for (int l = 0; l < NL; ++l) {
        u64 acc[4][8];
        #pragma unroll
        for (int q = 0; q < 4; ++q)
            #pragma unroll
            for (int i = 0; i < 8; ++i) acc[q][i] = 0ull;

        #pragma unroll 2
        for (int r = 0; r < 8; ++r, ++c) {
            stage_chunk(Ws + ((r + 1) & 1) * CHUNK_FLOATS, chunk_src(c + 1, Wh), tid);
            cp_wait<1>();
            __syncthreads();

            const float* wb = Ws + (r & 1) * CHUNK_FLOATS + (lane << 2);
            const u64* tf = tabF + (r << 5);
            #pragma unroll 4
            for (int kl = 0; kl < CHUNK; ++kl) {
                float4 wA = *(const float4*)(wb + kl * H);
                float4 wB = *(const float4*)(wb + kl * H + 128);
                u64 w0 = pack2(wA.x, wA.x), w1 = pack2(wA.y, wA.y);
                u64 w2 = pack2(wA.z, wA.z), w3 = pack2(wA.w, wA.w);
                u64 w4 = pack2(wB.x, wB.x), w5 = pack2(wB.y, wB.y);
                u64 w6 = pack2(wB.z, wB.z), w7 = pack2(wB.w, wB.w);
                #pragma unroll
                for (int q = 0; q < 4; ++q) {
                    u64 b = tf[(q << 8) + kl];
                    acc[q][0] = ffma2(b, w0, acc[q][0]);
                    acc[q][1] = ffma2(b, w1, acc[q][1]);
                    acc[q][2] = ffma2(b, w2, acc[q][2]);
                    acc[q][3] = ffma2(b, w3, acc[q][3]);
                    acc[q][4] = ffma2(b, w4, acc[q][4]);
                    acc[q][5] = ffma2(b, w5, acc[q][5]);
                    acc[q][6] = ffma2(b, w6, acc[q][6]);
                    acc[q][7] = ffma2(b, w7, acc[q][7]);
                }
            }
            __syncthreads();
        }

        // epilogue: bias AFTER reduction, relu, record mask
        u64 Ml = 0;
        if (l < NL - 1) {
            #pragma unroll
            for (int i = 0; i < 8; ++i) {
                int j = JIDX(i);
                float bb = __ldg(b_h + l * H + j);
                #pragma unroll
                for (int q = 0; q < 4; ++q) {
                    float lo, hi; unpack2(acc[q][i], lo, hi);
                    float alo = lo + bb, ahi = hi + bb;
                    bool mlo = alo > 0.f, mhi = ahi > 0.f;
                    Ml |= (mlo ? MBIT(i, q, 0) : 0ull) | (mhi ? MBIT(i, q, 1) : 0ull);
                    tabF[(q << 8) + j] = pack2(mlo ? alo : 0.f, mhi ? ahi : 0.f);
                }
            }
            __syncwarp();
        } else {
            // last layer: no table write; fold h into packed p-output partials
            #pragma unroll
            for (int i = 0; i < 8; ++i) {
                int j = JIDX(i);
                float bb = __ldg(b_h + l * H + j);
                float wo1 = __ldg(Wout + 2 * j + 1);
                u64 wo1d = pack2(wo1, wo1);
                #pragma unroll
                for (int q = 0; q < 4; ++q) {
                    float lo, hi; unpack2(acc[q][i], lo, hi);
                    float alo = lo + bb, ahi = hi + bb;
                    bool mlo = alo > 0.f, mhi = ahi > 0.f;
                    Ml |= (mlo ? MBIT(i, q, 0) : 0ull) | (mhi ? MBIT(i, q, 1) : 0ull);
                    ppq[q] = ffma2(pack2(mlo ? alo : 0.f, mhi ? ahi : 0.f), wo1d, ppq[q]);
                }
            }
        }
        Mh[l] = Ml;
    }

    // ---------------- backward init: masked cotangents at layer-3 output ----------------
    #pragma unroll
    for (int i = 0; i < 8; ++i) {
        int j = JIDX(i);
        float a0 = __ldg(Wout + 2 * j);       // psi stream
        float a1 = __ldg(Wout + 2 * j + 1);   // p stream
        #pragma unroll
        for (int q = 0; q < 4; ++q) {
            bool mlo = (Mh[3] & MBIT(i, q, 0)) != 0ull;
            bool mhi = (Mh[3] & MBIT(i, q, 1)) != 0ull;
            tb0[(q << 8) + j] = pack2(mlo ? a0 : 0.f, mhi ? a0 : 0.f);
            tb1[(q << 8) + j] = pack2(mlo ? a1 : 0.f, mhi ? a1 : 0.f);
        }
    }
    __syncwarp();

    // ---------------- backward hidden layers ----------------
    u64 na0[4][8], na1[4][8];

    #pragma unroll 1
    for (int bl = 3; bl >= 0; --bl) {
        #pragma unroll
        for (int q = 0; q < 4; ++q)
            #pragma unroll
            for (int i = 0; i < 8; ++i) { na0[q][i] = 0ull; na1[q][i] = 0ull; }

        #pragma unroll 2
        for (int r = 0; r < 8; ++r, ++c) {
            if (c < 63) {
                stage_chunk(Ws + ((r + 1) & 1) * CHUNK_FLOATS, chunk_src(c + 1, Wh), tid);
                cp_wait<1>();
            } else {
                cp_wait<0>();
            }
            __syncthreads();

            const float* wb = Ws + (r & 1) * CHUNK_FLOATS + (lane << 2);
            const u64* t0 = tb0 + (r << 5);
            const u64* t1 = tb1 + (r << 5);
            #pragma unroll 4
            for (int kl = 0; kl < CHUNK; ++kl) {
                float4 wA = *(const float4*)(wb + kl * H);
                float4 wB = *(const float4*)(wb + kl * H + 128);
                u64 w0 = pack2(wA.x, wA.x), w1 = pack2(wA.y, wA.y);
                u64 w2 = pack2(wA.z, wA.z), w3 = pack2(wA.w, wA.w);
                u64 w4 = pack2(wB.x, wB.x), w5 = pack2(wB.y, wB.y);
                u64 w6 = pack2(wB.z, wB.z), w7 = pack2(wB.w, wB.w);
                #pragma unroll
                for (int q = 0; q < 4; ++q) {
                    u64 b0 = t0[(q << 8) + kl];
                    u64 b1 = t1[(q << 8) + kl];
                    na0[q][0] = ffma2(b0, w0, na0[q][0]);
                    na0[q][1] = ffma2(b0, w1, na0[q][1]);
                    na0[q][2] = ffma2(b0, w2, na0[q][2]);
                    na0[q][3] = ffma2(b0, w3, na0[q][3]);
                    na0[q][4] = ffma2(b0, w4, na0[q][4]);
                    na0[q][5] = ffma2(b0, w5, na0[q][5]);
                    na0[q][6] = ffma2(b0, w6, na0[q][6]);
                    na0[q][7] = ffma2(b0, w7, na0[q][7]);
                    na1[q][0] = ffma2(b1, w0, na1[q][0]);
                    na1[q][1] = ffma2(b1, w1, na1[q][1]);
                    na1[q][2] = ffma2(b1, w2, na1[q][2]);
                    na1[q][3] = ffma2(b1, w3, na1[q][3]);
                    na1[q][4] = ffma2(b1, w4, na1[q][4]);
                    na1[q][5] = ffma2(b1, w5, na1[q][5]);
                    na1[q][6] = ffma2(b1, w6, na1[q][6]);
                    na1[q][7] = ffma2(b1, w7, na1[q][7]);
                }
            }
            __syncthreads();
        }

        if (bl > 0) {   // mask by previous layer and refill tables
            u64 Mp = Mh[bl - 1];
            #pragma unroll
            for (int i = 0; i < 8; ++i) {
                int j = JIDX(i);
                #pragma unroll
                for (int q = 0; q < 4; ++q) {
                    bool mlo = (Mp & MBIT(i, q, 0)) != 0ull;
                    bool mhi = (Mp & MBIT(i, q, 1)) != 0ull;
                    float l0, h0, l1, h1;
                    unpack2(na0[q][i], l0, h0);
                    unpack2(na1[q][i], l1, h1);
                    tb0[(q << 8) + j] = pack2(mlo ? l0 : 0.f, mhi ? h0 : 0.f);
                    tb1[(q << 8) + j] = pack2(mlo ? l1 : 0.f, mhi ? h1 : 0.f);
                }
            }
            __syncwarp();
        }
    }

    // ---------------- input-layer backward + outputs ----------------
    float su[WP], sv[WP], sf[WP], sg[WP], pp[WP];
    #pragma unroll
    for (int p = 0; p < WP; ++p) { su[p] = sv[p] = sf[p] = sg[p] = 0.f; }
    #pragma unroll
    for (int q = 0; q < 4; ++q) unpack2(ppq[q], pp[2 * q], pp[2 * q + 1]);

    #pragma unroll
    for (int i = 0; i < 8; ++i) {
        int j = JIDX(i);
        float wx = __ldg(Win + j);
        float wy = __ldg(Win + H + j);
        #pragma unroll
        for (int q = 0; q < 4; ++q) {
            float g0[2], g1[2];
            unpack2(na0[q][i], g0[0], g0[1]);
            unpack2(na1[q][i], g1[0], g1[1]);
            #pragma unroll
            for (int hh = 0; hh < 2; ++hh) {
                int p = 2 * q + hh;
                bool m = (Mi & MBIT(i, q, hh)) != 0ull;
                float r0 = m ? g0[hh] : 0.f;
                float r1 = m ? g1[hh] : 0.f;
                su[p] = fmaf(wy, r0, su[p]);
                sv[p] = fmaf(wx, r0, sv[p]);
                sf[p] = fmaf(wx, r1, sf[p]);
                sg[p] = fmaf(wy, r1, sg[p]);
            }
        }
    }

    #pragma unroll
    for (int off = 16; off > 0; off >>= 1) {
        #pragma unroll
        for (int p = 0; p < WP; ++p) {
            su[p] += __shfl_xor_sync(0xffffffffu, su[p], off);
            sv[p] += __shfl_xor_sync(0xffffffffu, sv[p], off);
            sf[p] += __shfl_xor_sync(0xffffffffu, sf[p], off);
            sg[p] += __shfl_xor_sync(0xffffffffu, sg[p], off);
            pp[p] += __shfl_xor_sync(0xffffffffu, pp[p], off);
        }
    }
    if (lane == 0) {
        float bo1 = __ldg(b_out + 1);
        #pragma unroll
        for (int p = 0; p < WP; ++p) {
            int pt = base + p;
            out[0 * NPTS + pt] =  su[p];
            out[1 * NPTS + pt] = -sv[p];
            out[2 * NPTS + pt] =  pp[p] + bo1;
            out[3 * NPTS + pt] =  sf[p];
            out[4 * NPTS + pt] =  sg[p];
        }
    }
}

extern "C" void kernel_launch(void* const* d_in, const int* in_sizes, int n_in,
                              void* d_out, int out_size)
{
    const float* x     = (const float*)d_in[0];
    const float* y     = (const float*)d_in[1];
    const float* t     = (const float*)d_in[2];
    const float* Win   = (const float*)d_in[3];
    const float* b_in  = (const float*)d_in[4];
    const float* Wh    = (const float*)d_in[5];
    const float* b_h   = (const float*)d_in[6];
    const float* Wout  = (const float*)d_in[7];
    const float* b_out = (const float*)d_in[8];
    float* out = (float*)d_out;

    prep_kernel<<<(NL * H * H) / THREADS, THREADS>>>(Wh);

    // 64KB weight double-buffer + 128KB per-warp tables = 192KB
    const int smem = (2 * CHUNK_FLOATS) * (int)sizeof(float) + WARPS * 2048 * (int)sizeof(u64);
    cudaFuncSetAttribute(pinn_kernel, cudaFuncAttributeMaxDynamicSharedMemorySize, smem);
    pinn_kernel<<<NPTS / PTS_PER_CTA, THREADS, smem>>>(x, y, t, Win, b_in, Wh, b_h,
                                                       Wout, b_out, out);
}